// round 10
// baseline (speedup 1.0000x reference)
#include <cuda_runtime.h>

// GenLoss, fused single kernel, two-level overlapped reduction tree.
// combined = mean_b( masked-mean_c( MAE(out,target)[b,c] ) ) - 0.01*mean(labels)/(epoch+1)
//
// 768 image blocks + 8 label blocks + 1 dedicated finalizer (777 total; one
// wave: 8 blocks/SM * 148 SMs = 1184 slots >= 777).
// Level 1: each image block writes its partial; the 16th arriver per plane
//   (per-plane counter, distinct address) folds that plane's 16 partials in
//   fixed order -> overlapped with remaining streaming. Same for labels.
// Level 2: finalizer polls ONE counter with ONE thread at 128ns (R8's lesson:
//   poll pressure starves co-resident streamers), then folds just 48 plane
//   sums + 1 label total. All fold orders are fixed -> deterministic.

#define PLANES      48
#define BPP         16
#define RBLOCKS     (PLANES * BPP)          // 768
#define LBLOCKS     8
#define TOTAL_BLK   (RBLOCKS + LBLOCKS + 1) // 777
#define FIN_BLK     (TOTAL_BLK - 1)
#define THREADS     256
#define PLANE_ELEMS (512*512)
#define BLOCK_ELEMS (PLANE_ELEMS/BPP)          // 16384
#define VEC_ITERS   (BLOCK_ELEMS/(THREADS*4))  // 16
#define DONE_TARGET (PLANES + 1)               // 48 plane folds + 1 label fold

__device__ float g_psum[RBLOCKS];
__device__ float g_pmax[RBLOCKS];
__device__ float g_plane_sum[PLANES];
__device__ int   g_plane_valid[PLANES];
__device__ float g_lsum[LBLOCKS];
__device__ float g_lab_total;
__device__ int   g_plane_cnt[PLANES];   // zero-init; reset by each plane folder
__device__ int   g_lab_cnt;             // zero-init; reset by label folder
__device__ int   g_done;                // zero-init; reset by finalizer

__global__ void __launch_bounds__(THREADS, 8)
k_genloss(const float* __restrict__ out_img, const float* __restrict__ tgt_img,
          const float* __restrict__ labels, int n_labels,
          const int* __restrict__ epoch, float* __restrict__ out)
{
    const int tid = threadIdx.x;
    const int wid = tid >> 5;
    const int lid = tid & 31;
    const int bid = blockIdx.x;

    __shared__ float ss[THREADS / 32];
    __shared__ float sm[THREADS / 32];

    if (bid < RBLOCKS) {
        // ---- image MAE partial over 1/16th of one plane ----
        const int plane = bid / BPP;
        const int sub   = bid % BPP;
        const long base = (long)plane * PLANE_ELEMS + (long)sub * BLOCK_ELEMS;

        const float4* __restrict__ o = (const float4*)(out_img + base);
        const float4* __restrict__ t = (const float4*)(tgt_img + base);

        float s0 = 0.0f, s1 = 0.0f;   // two accumulators for FP ILP
        float m  = 0.0f;              // max |target| -> validity (FMNMX, alu pipe)
        #pragma unroll
        for (int j = 0; j < VEC_ITERS; j++) {
            float4 a = o[tid + j * THREADS];
            float4 b = t[tid + j * THREADS];
            s0 += fabsf(a.x - b.x) + fabsf(a.y - b.y);
            s1 += fabsf(a.z - b.z) + fabsf(a.w - b.w);
            m = fmaxf(m, fabsf(b.x)); m = fmaxf(m, fabsf(b.y));
            m = fmaxf(m, fabsf(b.z)); m = fmaxf(m, fabsf(b.w));
        }
        float s = s0 + s1;
        #pragma unroll
        for (int off = 16; off; off >>= 1) {
            s += __shfl_down_sync(0xffffffffu, s, off);
            m  = fmaxf(m, __shfl_down_sync(0xffffffffu, m, off));
        }
        if (lid == 0) { ss[wid] = s; sm[wid] = m; }
        __syncthreads();
        if (tid == 0) {
            float bs = 0.0f, bm = 0.0f;
            #pragma unroll
            for (int w = 0; w < THREADS / 32; w++) { bs += ss[w]; bm = fmaxf(bm, sm[w]); }
            g_psum[bid] = bs;
            g_pmax[bid] = bm;
            __threadfence();
            // level-1 arrival: last arriver folds this plane (overlapped with
            // other planes' streaming; fixed ascending order -> deterministic)
            if (atomicAdd(&g_plane_cnt[plane], 1) == BPP - 1) {
                __threadfence();
                float ps = 0.0f, pm = 0.0f;
                #pragma unroll
                for (int i = 0; i < BPP; i++) {
                    ps += g_psum[plane * BPP + i];
                    pm  = fmaxf(pm, g_pmax[plane * BPP + i]);
                }
                g_plane_sum[plane]   = ps;
                g_plane_valid[plane] = (pm > 0.0f);
                g_plane_cnt[plane]   = 0;        // reset for next replay
                __threadfence();
                atomicAdd(&g_done, 1);
            }
        }
        return;
    }

    if (bid < RBLOCKS + LBLOCKS) {
        // ---- label partial sum ----
        const int lb = bid - RBLOCKS;
        float s = 0.0f;
        for (int i = lb * THREADS + tid; i < n_labels; i += LBLOCKS * THREADS)
            s += labels[i];
        #pragma unroll
        for (int off = 16; off; off >>= 1)
            s += __shfl_down_sync(0xffffffffu, s, off);
        if (lid == 0) ss[wid] = s;
        __syncthreads();
        if (tid == 0) {
            float bs = 0.0f;
            #pragma unroll
            for (int w = 0; w < THREADS / 32; w++) bs += ss[w];
            g_lsum[lb] = bs;
            __threadfence();
            if (atomicAdd(&g_lab_cnt, 1) == LBLOCKS - 1) {
                __threadfence();
                float ls = 0.0f;
                #pragma unroll
                for (int i = 0; i < LBLOCKS; i++) ls += g_lsum[i];
                g_lab_total = ls;
                g_lab_cnt   = 0;
                __threadfence();
                atomicAdd(&g_done, 1);
            }
        }
        return;
    }

    // ================= finalizer (block 776, no other work) =================
    if (tid == 0) {
        volatile int* vd = &g_done;
        while (*vd != DONE_TARGET) __nanosleep(128);
        g_done = 0;                              // reset for next replay
    }
    __syncthreads();
    __threadfence();   // acquire: order reads after counter observation

    __shared__ float sps[PLANES];
    __shared__ int   spv[PLANES];
    if (tid < PLANES) {
        sps[tid] = g_plane_sum[tid];
        spv[tid] = g_plane_valid[tid];
    }
    __syncthreads();

    if (tid == 0) {
        const float lmean = g_lab_total / (float)n_labels;

        float img = 0.0f;
        #pragma unroll
        for (int b = 0; b < 16; b++) {
            float tot = 0.0f, cnt = 0.0f;
            #pragma unroll
            for (int c = 0; c < 3; c++) {
                const int p = b * 3 + c;
                if (spv[p]) { tot += sps[p] * (1.0f / (float)PLANE_ELEMS); cnt += 1.0f; }
            }
            img += (cnt > 0.0f) ? (tot / cnt) : 0.0f;
        }
        img *= (1.0f / 16.0f);

        out[0] = img + 0.01f * (-lmean) / (float)(epoch[0] + 1);
    }
}

extern "C" void kernel_launch(void* const* d_in, const int* in_sizes, int n_in,
                              void* d_out, int out_size)
{
    const float* labels  = (const float*)d_in[0];
    const float* out_img = (const float*)d_in[1];
    const float* tgt_img = (const float*)d_in[2];
    const int*   epoch   = (const int*)d_in[3];
    float*       out     = (float*)d_out;

    k_genloss<<<TOTAL_BLK, THREADS>>>(out_img, tgt_img, labels, in_sizes[0], epoch, out);
}

// round 11
// speedup vs baseline: 1.2938x; 1.2938x over previous
#include <cuda_runtime.h>

// GenLoss, fused single kernel, occupancy-1 layout to kill CTA-completion
// spread (B300 spread model: spr grows with oe*MLP_p1; at oe=1 it's ~1.10).
// combined = mean_b( masked-mean_c( MAE(out,target)[b,c] ) ) - 0.01*mean(labels)/(epoch+1)
//
// Grid = 145 blocks x 1024 threads, one per SM (<=148 -> all resident from
// t=0, single wave; spin-wait is deadlock-free):
//   blocks 0..143 : image MAE partials. 48 planes x 3 sub-blocks; each plane's
//                   64 chunks (4096 elems) split 22/21/21 -> perfect balance.
//   block  144    : label sum (tiny, overlapped with stream), then single-
//                   thread 256ns poll on ONE one-shot RED counter (R9-proven:
//                   no returning atomics, no multi-thread polling), then a
//                   fixed-order fold of the 144 partials. Deterministic.

#define PLANES      48
#define SUBS        3
#define RBLOCKS     (PLANES * SUBS)     // 144
#define FIN_BLK     RBLOCKS             // 144
#define TOTAL_BLK   (RBLOCKS + 1)       // 145
#define THREADS     1024
#define NWARP       (THREADS / 32)
#define PLANE_ELEMS (512*512)
#define CHUNK       (THREADS * 4)       // 4096 elems per iteration
#define CPP         (PLANE_ELEMS / CHUNK) // 64 chunks per plane

__device__ float g_psum[RBLOCKS];
__device__ int   g_pflag[RBLOCKS];
__device__ int   g_done;                // zero-init; reset by finalizer

__global__ void __launch_bounds__(THREADS, 1)
k_genloss(const float* __restrict__ out_img, const float* __restrict__ tgt_img,
          const float* __restrict__ labels, int n_labels,
          const int* __restrict__ epoch, float* __restrict__ out)
{
    const int tid = threadIdx.x;
    const int wid = tid >> 5;
    const int lid = tid & 31;
    const int bid = blockIdx.x;

    __shared__ float ss[NWARP];
    __shared__ int   sf[NWARP];

    if (bid < RBLOCKS) {
        // ---- image MAE partial ----
        const int plane = bid / SUBS;
        const int sub   = bid % SUBS;
        // chunk split 22/21/21 over 64 chunks
        const int c0  = (sub == 0) ? 0  : 22 + (sub - 1) * 21;
        const int nch = (sub == 0) ? 22 : 21;
        const long base = (long)plane * PLANE_ELEMS + (long)c0 * CHUNK;

        const float4* __restrict__ o = (const float4*)(out_img + base);
        const float4* __restrict__ t = (const float4*)(tgt_img + base);

        float s = 0.0f;
        int   flag = 0;
        #pragma unroll 4
        for (int j = 0; j < nch; j++) {
            float4 a = o[tid + j * THREADS];
            float4 b = t[tid + j * THREADS];
            s += fabsf(a.x - b.x) + fabsf(a.y - b.y)
               + fabsf(a.z - b.z) + fabsf(a.w - b.w);
            flag |= (b.x != 0.0f) | (b.y != 0.0f) | (b.z != 0.0f) | (b.w != 0.0f);
        }
        #pragma unroll
        for (int off = 16; off; off >>= 1) {
            s    += __shfl_down_sync(0xffffffffu, s, off);
            flag |= __shfl_down_sync(0xffffffffu, flag, off);
        }
        if (lid == 0) { ss[wid] = s; sf[wid] = flag; }
        __syncthreads();
        if (wid == 0) {
            s    = (lid < NWARP) ? ss[lid] : 0.0f;
            flag = (lid < NWARP) ? sf[lid] : 0;
            #pragma unroll
            for (int off = 16; off; off >>= 1) {
                s    += __shfl_down_sync(0xffffffffu, s, off);
                flag |= __shfl_down_sync(0xffffffffu, flag, off);
            }
            if (lid == 0) {
                g_psum[bid]  = s;
                g_pflag[bid] = flag;
                __threadfence();
                atomicAdd(&g_done, 1);   // fire-and-forget one-shot RED
            }
        }
        return;
    }

    // ================= block 144: labels + finalizer =================
    __shared__ float slab;
    {
        float s = 0.0f;
        for (int i = tid; i < n_labels; i += THREADS) s += labels[i];
        #pragma unroll
        for (int off = 16; off; off >>= 1)
            s += __shfl_down_sync(0xffffffffu, s, off);
        if (lid == 0) ss[wid] = s;
        __syncthreads();
        if (wid == 0) {
            s = (lid < NWARP) ? ss[lid] : 0.0f;
            #pragma unroll
            for (int off = 16; off; off >>= 1)
                s += __shfl_down_sync(0xffffffffu, s, off);
            if (lid == 0) slab = s;
        }
    }

    // single-thread low-pressure poll (R8 lesson: multi-thread polling starves
    // co-resident warps' LSU; here it also shares the SM with nothing hot)
    if (tid == 0) {
        volatile int* vd = &g_done;
        while (*vd != RBLOCKS) __nanosleep(256);
        g_done = 0;                       // reset for next graph replay
    }
    __syncthreads();
    __threadfence();   // acquire: order partial reads after counter observation

    __shared__ float sp[RBLOCKS];
    __shared__ int   sfl[RBLOCKS];
    __shared__ float plane_mae[PLANES];
    __shared__ int   plane_valid[PLANES];

    // parallel vectorized fetch: 36 float4 + 36 int4 loads, one round-trip
    const float4* ps4 = (const float4*)g_psum;
    const int4*   pf4 = (const int4*)g_pflag;
    if (tid < RBLOCKS / 4) {
        float4 v = ps4[tid];
        int4   f = pf4[tid];
        sp[tid * 4 + 0] = v.x;  sp[tid * 4 + 1] = v.y;
        sp[tid * 4 + 2] = v.z;  sp[tid * 4 + 3] = v.w;
        sfl[tid * 4 + 0] = f.x; sfl[tid * 4 + 1] = f.y;
        sfl[tid * 4 + 2] = f.z; sfl[tid * 4 + 3] = f.w;
    }
    __syncthreads();

    if (tid < PLANES) {
        float s = sp[tid * SUBS] + sp[tid * SUBS + 1] + sp[tid * SUBS + 2];
        int   f = sfl[tid * SUBS] | sfl[tid * SUBS + 1] | sfl[tid * SUBS + 2];
        plane_mae[tid]   = s * (1.0f / (float)PLANE_ELEMS);
        plane_valid[tid] = f;
    }
    __syncthreads();

    if (tid == 0) {
        const float lmean = slab / (float)n_labels;

        float img = 0.0f;
        #pragma unroll
        for (int b = 0; b < 16; b++) {
            float tot = 0.0f, cnt = 0.0f;
            #pragma unroll
            for (int c = 0; c < 3; c++) {
                const int p = b * 3 + c;
                if (plane_valid[p]) { tot += plane_mae[p]; cnt += 1.0f; }
            }
            img += (cnt > 0.0f) ? (tot / cnt) : 0.0f;
        }
        img *= (1.0f / 16.0f);

        out[0] = img + 0.01f * (-lmean) / (float)(epoch[0] + 1);
    }
}

extern "C" void kernel_launch(void* const* d_in, const int* in_sizes, int n_in,
                              void* d_out, int out_size)
{
    const float* labels  = (const float*)d_in[0];
    const float* out_img = (const float*)d_in[1];
    const float* tgt_img = (const float*)d_in[2];
    const int*   epoch   = (const int*)d_in[3];
    float*       out     = (float*)d_out;

    k_genloss<<<TOTAL_BLK, THREADS>>>(out_img, tgt_img, labels, in_sizes[0], epoch, out);
}